// round 10
// baseline (speedup 1.0000x reference)
#include <cuda_runtime.h>
#include <cuda_bf16.h>
#include <cstdint>
#include <math.h>

#define Bc 8
#define Lc 1024
#define Kc 1024
#define Dc 128
#define Sc 16
#define ML (Bc * Lc)

// ---------------- device scratch ----------------
__device__ float g_W2[Dc * 2 * Dc];
__device__ float g_b2[2 * Dc];
__device__ float g_ar[Dc * Sc];
__device__ float g_mag2[Dc * Sc];
__device__ float g_w[Dc * Sc];
__device__ float g_rnorm[ML];
__device__ float g_t[ML * Dc];
__device__ float g_coefT[Bc * Dc * Kc];          // [b][d][k]
__device__ __nv_bfloat16 d_EhT[Bc * Kc * Lc];    // E^T hi  [b][k][l]
__device__ __nv_bfloat16 d_ElT[Bc * Kc * Lc];    // E^T lo
__device__ __nv_bfloat16 d_Eh[Bc * Lc * Kc];     // E hi    [b][l][k]
__device__ __nv_bfloat16 d_El[Bc * Lc * Kc];     // E lo
__device__ __nv_bfloat16 d_u2Th[Bc * Dc * Lc];   // u2^T hi [b][d][l]
__device__ __nv_bfloat16 d_u2Tl[Bc * Dc * Lc];
__device__ __nv_bfloat16 d_VTh[Bc * Dc * Kc];    // V^T hi  [b][d][k]
__device__ __nv_bfloat16 d_VTl[Bc * Dc * Kc];

__device__ __forceinline__ float fsigmoid(float v) { return 1.0f / (1.0f + __expf(-v)); }

__device__ __forceinline__ void split2(float v, __nv_bfloat16& h, __nv_bfloat16& l) {
    h = __float2bfloat16(v);
    l = __float2bfloat16(v - __bfloat162float(h));
}
__device__ __forceinline__ void split4(float4 v, uint2& H, uint2& L) {
    __nv_bfloat162 h01, h23, l01, l23;
    split2(v.x, h01.x, l01.x);
    split2(v.y, h01.y, l01.y);
    split2(v.z, h23.x, l23.x);
    split2(v.w, h23.y, l23.y);
    H.x = *(uint32_t*)&h01; H.y = *(uint32_t*)&h23;
    L.x = *(uint32_t*)&l01; L.y = *(uint32_t*)&l23;
}

__device__ __forceinline__ void mma_bf16(float* c, const uint32_t* a, const uint32_t* b) {
    asm volatile(
        "mma.sync.aligned.m16n8k16.row.col.f32.bf16.bf16.f32 "
        "{%0,%1,%2,%3}, {%4,%5,%6,%7}, {%8,%9}, {%0,%1,%2,%3};"
        : "+f"(c[0]), "+f"(c[1]), "+f"(c[2]), "+f"(c[3])
        : "r"(a[0]), "r"(a[1]), "r"(a[2]), "r"(a[3]), "r"(b[0]), "r"(b[1]));
}

__device__ __forceinline__ void cp16(uint32_t dst, const void* src) {
    asm volatile("cp.async.cg.shared.global [%0], [%1], 16;" :: "r"(dst), "l"(src));
}
#define CP_COMMIT() asm volatile("cp.async.commit_group;" ::: "memory")
template <int N>
__device__ __forceinline__ void cp_wait() {
    asm volatile("cp.async.wait_group %0;" :: "n"(N) : "memory");
}

// ---------------- prep ----------------
__global__ void prep_kernel(const float* __restrict__ bn_g, const float* __restrict__ bn_b,
                            const float* __restrict__ bn_m, const float* __restrict__ bn_v,
                            const float* __restrict__ W_in, const float* __restrict__ b_in,
                            const float* __restrict__ logD, const float* __restrict__ Bp,
                            const float* __restrict__ Cp, const float* __restrict__ logAr,
                            const float* __restrict__ Aim) {
    int t = threadIdx.x;
    __shared__ float sc[Dc], sh[Dc];
    if (t < Dc) {
        float s = bn_g[t] * rsqrtf(bn_v[t] + 1e-5f);
        sc[t] = s;
        sh[t] = bn_b[t] - bn_m[t] * s;
    }
    __syncthreads();
    for (int i = t; i < Dc * 2 * Dc; i += 256) g_W2[i] = sc[i / (2 * Dc)] * W_in[i];
    {
        float acc = b_in[t];
        for (int d = 0; d < Dc; ++d) acc = fmaf(sh[d], W_in[d * 2 * Dc + t], acc);
        g_b2[t] = acc;
    }
    for (int i = t; i < Dc * Sc; i += 256) {
        int d = i / Sc;
        float delta = expf(logD[d]);
        float aR = -expf(logAr[i]);
        float mag = expf(-1e-3f + delta * aR);
        float ang = delta * Aim[i];
        float ar = mag * cosf(ang);
        float ai = mag * sinf(ang);
        g_ar[i] = ar;
        g_mag2[i] = ar * ar + ai * ai;
        g_w[i] = delta * Bp[i] * Cp[i];
    }
}

// ---------------- rnorm ----------------
__global__ void rnorm_kernel(const float* __restrict__ E) {
    int row = blockIdx.x * 8 + (threadIdx.x >> 5);
    int lane = threadIdx.x & 31;
    const float4* p = (const float4*)(E + (size_t)row * Kc);
    float s = 0.0f;
    #pragma unroll 4
    for (int i = lane; i < Kc / 4; i += 32) {
        float4 v = p[i];
        s += v.x * v.x + v.y * v.y + v.z * v.z + v.w * v.w;
    }
    #pragma unroll
    for (int o = 16; o; o >>= 1) s += __shfl_xor_sync(0xffffffffu, s, o);
    if (lane == 0) g_rnorm[row] = rsqrtf(s);
}

// ---------------- etsplit: E -> Eh/El (straight) + EhT/ElT (transposed) ----------------
__global__ void etsplit_kernel(const float* __restrict__ E) {
    __shared__ float Sg[32 * 132];
    int b = blockIdx.z, l0 = blockIdx.y * 128, k0 = blockIdx.x * 32;
    int t = threadIdx.x;
    int kq = t & 7, lr = t >> 3;
    #pragma unroll
    for (int j = 0; j < 4; ++j) {
        int l = j * 32 + lr;
        size_t go = ((size_t)(b * Lc + l0 + l)) * Kc + k0 + kq * 4;
        float4 v = *(const float4*)(E + go);
        uint2 H, L;
        split4(v, H, L);
        *(uint2*)(d_Eh + go) = H;
        *(uint2*)(d_El + go) = L;
        Sg[(kq * 4 + 0) * 132 + l] = v.x;
        Sg[(kq * 4 + 1) * 132 + l] = v.y;
        Sg[(kq * 4 + 2) * 132 + l] = v.z;
        Sg[(kq * 4 + 3) * 132 + l] = v.w;
    }
    __syncthreads();
    int k = t >> 3, seg = t & 7;
    __align__(16) __nv_bfloat16 hh[16], ll[16];
    #pragma unroll
    for (int i = 0; i < 4; ++i) {
        float4 v = *(const float4*)&Sg[k * 132 + seg * 16 + i * 4];
        split2(v.x, hh[i * 4 + 0], ll[i * 4 + 0]);
        split2(v.y, hh[i * 4 + 1], ll[i * 4 + 1]);
        split2(v.z, hh[i * 4 + 2], ll[i * 4 + 2]);
        split2(v.w, hh[i * 4 + 3], ll[i * 4 + 3]);
    }
    size_t ob = ((size_t)(b * Kc + k0 + k)) * Lc + l0 + seg * 16;
    *(uint4*)(d_EhT + ob) = *(uint4*)hh;
    *(uint4*)(d_EhT + ob + 8) = *(uint4*)(hh + 8);
    *(uint4*)(d_ElT + ob) = *(uint4*)ll;
    *(uint4*)(d_ElT + ob + 8) = *(uint4*)(ll + 8);
}

// ---------------- coef: coefT[b][d][k] ----------------
__global__ void coef_kernel(const float* __restrict__ EigVals) {
    int b = blockIdx.z, d = blockIdx.y;
    int kk = blockIdx.x * 256 + threadIdx.x;
    __shared__ float sar[Sc], sm2[Sc], sw[Sc];
    if (threadIdx.x < Sc) {
        sar[threadIdx.x] = g_ar[d * Sc + threadIdx.x];
        sm2[threadIdx.x] = g_mag2[d * Sc + threadIdx.x];
        sw[threadIdx.x] = g_w[d * Sc + threadIdx.x];
    }
    __syncthreads();
    float ev = 1.0f - EigVals[b * Kc + kk];
    float ev2 = ev * ev;
    float c = 0.0f;
    #pragma unroll
    for (int s = 0; s < Sc; ++s) {
        float p = ev * sar[s];
        float r = ev2 * sm2[s];
        c = fmaf(sw[s], __fdividef(p - r, 1.0f - 2.0f * p + r), c);
    }
    g_coefT[((size_t)(b * Dc + d)) * Kc + kk] = c;
}

// ---------------- uproj ----------------
__global__ void uproj_kernel(const float* __restrict__ x) {
    int r0 = blockIdx.x * 64;
    __shared__ __align__(16) float SU[5188];
    float* As = SU;
    float* Bs = SU + 1088;
    int tid = threadIdx.x;
    int tx = tid & 31, ty = tid >> 5;
    float acc[4][8] = {};
    int am = tid >> 2, akq = tid & 3;
    int bn4 = tid & 63, bli = tid >> 6;

    for (int kt = 0; kt < Dc; kt += 16) {
        float4 av = make_float4(0.f, 0.f, 0.f, 0.f);
        if (tid < 256) av = *(const float4*)(x + (size_t)(r0 + am) * Dc + kt + akq * 4);
        float4 bv0 = *(const float4*)(g_W2 + (kt + bli) * 256 + bn4 * 4);
        float4 bv1 = *(const float4*)(g_W2 + (kt + bli + 8) * 256 + bn4 * 4);
        __syncthreads();
        if (tid < 256) {
            As[(akq * 4 + 0) * 68 + am] = av.x;
            As[(akq * 4 + 1) * 68 + am] = av.y;
            As[(akq * 4 + 2) * 68 + am] = av.z;
            As[(akq * 4 + 3) * 68 + am] = av.w;
        }
        *(float4*)&Bs[bli * 256 + bn4 * 4] = bv0;
        *(float4*)&Bs[(bli + 8) * 256 + bn4 * 4] = bv1;
        __syncthreads();
        #pragma unroll
        for (int kk = 0; kk < 16; ++kk) {
            const float4 a = *(const float4*)&As[kk * 68 + ty * 4];
            const float4 p = *(const float4*)&Bs[kk * 256 + tx * 4];
            const float4 q = *(const float4*)&Bs[kk * 256 + tx * 4 + 128];
            float av4[4] = {a.x, a.y, a.z, a.w};
            float bv8[8] = {p.x, p.y, p.z, p.w, q.x, q.y, q.z, q.w};
            #pragma unroll
            for (int i = 0; i < 4; ++i)
                #pragma unroll
                for (int j = 0; j < 8; ++j)
                    acc[i][j] = fmaf(av4[i], bv8[j], acc[i][j]);
        }
    }
    int b = r0 >> 10, l0 = r0 & 1023;
    #pragma unroll
    for (int h = 0; h < 2; ++h) {
        __syncthreads();
        if ((tx >> 4) == h) {
            #pragma unroll
            for (int i = 0; i < 4; ++i) {
                int row = r0 + ty * 4 + i;
                float rn = g_rnorm[row];
                int l = ty * 4 + i;
                #pragma unroll
                for (int jj = 0; jj < 4; ++jj) {
                    int n = tx * 4 + jj;
                    float lo = acc[i][jj] + g_b2[n];
                    float hi = acc[i][jj + 4] + g_b2[n + 128];
                    SU[(n - h * 64) * 65 + l] = lo * hi * fsigmoid(hi) * rn;
                }
            }
        }
        __syncthreads();
        int dd = tid >> 3, sg = tid & 7;
        __align__(16) __nv_bfloat16 hh[8], ll[8];
        #pragma unroll
        for (int q = 0; q < 8; ++q) split2(SU[dd * 65 + sg * 8 + q], hh[q], ll[q]);
        size_t ob = ((size_t)(b * Dc + h * 64 + dd)) * Lc + l0 + sg * 8;
        *(uint4*)(d_u2Th + ob) = *(uint4*)hh;
        *(uint4*)(d_u2Tl + ob) = *(uint4*)ll;
    }
}

// ---------------- TN HMMA template: 64x64 tile, k-chunk 32, 3-stage cp.async ----------------
// smem stage: Ah[64][40] Al Bh Bl (halfs). RS=40 -> conflict-free LDS.32 fragments.
#define RS 40
#define ASZ (64 * RS)               // 2560 halfs
#define ASZB (ASZ * 2)              // 5120 B
#define STGB (4 * ASZB)             // 20480 B / stage
#define NSTG 3
#define SMEM_BYTES (NSTG * STGB)    // 61440

__device__ __forceinline__ void tn_issue(uint32_t sb, const __nv_bfloat16* Ah,
                                         const __nv_bfloat16* Al, const __nv_bfloat16* Bh,
                                         const __nv_bfloat16* Bl, int tid, int kc0) {
    int row = tid >> 2, seg = tid & 3;
    uint32_t off = (uint32_t)(row * RS + seg * 8) * 2;
    size_t go = (size_t)row * 1024 + kc0 + seg * 8;
    cp16(sb + off, Ah + go);
    cp16(sb + ASZB + off, Al + go);
    cp16(sb + 2 * ASZB + off, Bh + go);
    cp16(sb + 3 * ASZB + off, Bl + go);
}

__device__ __forceinline__ void tn_compute(const __nv_bfloat16* s, int wid, int lane,
                                           float C[2][2][4]) {
    const __nv_bfloat16* sAh = s;
    const __nv_bfloat16* sAl = s + ASZ;
    const __nv_bfloat16* sBh = s + 2 * ASZ;
    const __nv_bfloat16* sBl = s + 3 * ASZ;
    int wm = wid & 1, wn = wid >> 1;
    int lr = lane >> 2, lc = (lane & 3) * 2;
    #pragma unroll
    for (int ks = 0; ks < 2; ++ks) {
        int acol = ks * 16 + lc;
        uint32_t ah[2][4], al[2][4], bh[2][2], bl[2][2];
        #pragma unroll
        for (int mi = 0; mi < 2; ++mi) {
            int rb = wm * 32 + mi * 16 + lr;
            ah[mi][0] = *(const uint32_t*)(sAh + rb * RS + acol);
            ah[mi][1] = *(const uint32_t*)(sAh + (rb + 8) * RS + acol);
            ah[mi][2] = *(const uint32_t*)(sAh + rb * RS + acol + 8);
            ah[mi][3] = *(const uint32_t*)(sAh + (rb + 8) * RS + acol + 8);
            al[mi][0] = *(const uint32_t*)(sAl + rb * RS + acol);
            al[mi][1] = *(const uint32_t*)(sAl + (rb + 8) * RS + acol);
            al[mi][2] = *(const uint32_t*)(sAl + rb * RS + acol + 8);
            al[mi][3] = *(const uint32_t*)(sAl + (rb + 8) * RS + acol + 8);
        }
        #pragma unroll
        for (int ni = 0; ni < 2; ++ni) {
            int nr = wn * 16 + ni * 8 + lr;
            bh[ni][0] = *(const uint32_t*)(sBh + nr * RS + acol);
            bh[ni][1] = *(const uint32_t*)(sBh + nr * RS + acol + 8);
            bl[ni][0] = *(const uint32_t*)(sBl + nr * RS + acol);
            bl[ni][1] = *(const uint32_t*)(sBl + nr * RS + acol + 8);
        }
        #pragma unroll
        for (int mi = 0; mi < 2; ++mi)
            #pragma unroll
            for (int ni = 0; ni < 2; ++ni) {
                mma_bf16(C[mi][ni], ah[mi], bh[ni]);
                mma_bf16(C[mi][ni], ah[mi], bl[ni]);
                mma_bf16(C[mi][ni], al[mi], bh[ni]);
            }
    }
}

#define TN_MAINLOOP(Ah, Al, Bh, Bl)                                                  \
    tn_issue(sb, Ah, Al, Bh, Bl, tid, 0);                                            \
    CP_COMMIT();                                                                     \
    tn_issue(sb + STGB, Ah, Al, Bh, Bl, tid, 32);                                    \
    CP_COMMIT();                                                                     \
    for (int c = 0; c < 32; ++c) {                                                   \
        if (c < 30) cp_wait<1>(); else cp_wait<0>();                                 \
        __syncthreads();                                                             \
        tn_compute((const __nv_bfloat16*)(smraw + (c % 3) * STGB), wid, lane, C);    \
        __syncthreads();                                                             \
        if (c + 2 < 32) {                                                            \
            tn_issue(sb + ((c + 2) % 3) * STGB, Ah, Al, Bh, Bl, tid, (c + 2) * 32);  \
            CP_COMMIT();                                                             \
        }                                                                            \
    }

// GEMM1: D[k,d] = sum_l EhT[k][l]*u2T[d][l]; epilogue *coef -> VT hi/lo
__global__ void __launch_bounds__(256, 2) gemm1_hmma() {
    extern __shared__ __align__(16) char smraw[];
    uint32_t sb = (uint32_t)__cvta_generic_to_shared(smraw);
    int tid = threadIdx.x, wid = tid >> 5, lane = tid & 31;
    int b = blockIdx.z, k0 = blockIdx.x * 64, d0 = blockIdx.y * 64;

    const __nv_bfloat16* Ah = d_EhT + ((size_t)(b * Kc + k0)) * Lc;
    const __nv_bfloat16* Al = d_ElT + ((size_t)(b * Kc + k0)) * Lc;
    const __nv_bfloat16* Bh = d_u2Th + ((size_t)(b * Dc + d0)) * Lc;
    const __nv_bfloat16* Bl = d_u2Tl + ((size_t)(b * Dc + d0)) * Lc;

    float C[2][2][4] = {};
    TN_MAINLOOP(Ah, Al, Bh, Bl);

    __syncthreads();
    float* Cst = (float*)smraw;  // 64 x 65
    {
        int wm = wid & 1, wn = wid >> 1;
        int lr = lane >> 2, lc = (lane & 3) * 2;
        #pragma unroll
        for (int mi = 0; mi < 2; ++mi)
            #pragma unroll
            for (int ni = 0; ni < 2; ++ni) {
                int rr = wm * 32 + mi * 16 + lr;
                int cc = wn * 16 + ni * 8 + lc;
                Cst[rr * 65 + cc] = C[mi][ni][0];
                Cst[rr * 65 + cc + 1] = C[mi][ni][1];
                Cst[(rr + 8) * 65 + cc] = C[mi][ni][2];
                Cst[(rr + 8) * 65 + cc + 1] = C[mi][ni][3];
            }
    }
    __syncthreads();
    #pragma unroll
    for (int rr = 0; rr < 8; ++rr) {
        int d = wid * 8 + rr;
        const float* cf = g_coefT + (size_t)(b * Dc + d0 + d) * Kc + k0;
        __nv_bfloat16* vh = d_VTh + (size_t)(b * Dc + d0 + d) * Kc + k0;
        __nv_bfloat16* vl = d_VTl + (size_t)(b * Dc + d0 + d) * Kc + k0;
        #pragma unroll
        for (int it = 0; it < 2; ++it) {
            int k = it * 32 + lane;
            float v = Cst[k * 65 + d] * cf[k];
            __nv_bfloat16 h, l;
            split2(v, h, l);
            vh[k] = h;
            vl[k] = l;
        }
    }
}

// GEMM2: D[l,d] = sum_k Eh[l][k]*VT[d][k]; epilogue silu*rnorm -> g_t
__global__ void __launch_bounds__(256, 2) gemm2_hmma() {
    extern __shared__ __align__(16) char smraw[];
    uint32_t sb = (uint32_t)__cvta_generic_to_shared(smraw);
    int tid = threadIdx.x, wid = tid >> 5, lane = tid & 31;
    int b = blockIdx.z, l0 = blockIdx.x * 64, d0 = blockIdx.y * 64;

    const __nv_bfloat16* Ah = d_Eh + ((size_t)(b * Lc + l0)) * Kc;
    const __nv_bfloat16* Al = d_El + ((size_t)(b * Lc + l0)) * Kc;
    const __nv_bfloat16* Bh = d_VTh + ((size_t)(b * Dc + d0)) * Kc;
    const __nv_bfloat16* Bl = d_VTl + ((size_t)(b * Dc + d0)) * Kc;

    float C[2][2][4] = {};
    TN_MAINLOOP(Ah, Al, Bh, Bl);

    int wm = wid & 1, wn = wid >> 1;
    int lr = lane >> 2, lc = (lane & 3) * 2;
    #pragma unroll
    for (int mi = 0; mi < 2; ++mi) {
        int lg0 = l0 + wm * 32 + mi * 16 + lr;
        float rn0 = g_rnorm[b * Lc + lg0];
        float rn1 = g_rnorm[b * Lc + lg0 + 8];
        float* t0 = g_t + ((size_t)(b * Lc + lg0)) * Dc;
        float* t1 = t0 + 8 * Dc;
        #pragma unroll
        for (int ni = 0; ni < 2; ++ni) {
            int d = d0 + wn * 16 + ni * 8 + lc;
            float v0 = C[mi][ni][0] * rn0, v1 = C[mi][ni][1] * rn0;
            float v2 = C[mi][ni][2] * rn1, v3 = C[mi][ni][3] * rn1;
            *(float2*)(t0 + d) = make_float2(v0 * fsigmoid(v0), v1 * fsigmoid(v1));
            *(float2*)(t1 + d) = make_float2(v2 * fsigmoid(v2), v3 * fsigmoid(v3));
        }
    }
}

// ---------------- out_proj ----------------
__global__ void outproj_kernel(const float* __restrict__ Wout, const float* __restrict__ bout,
                               float* __restrict__ y) {
    int r0 = blockIdx.x * 64;
    __shared__ __align__(16) float As[16 * 68];
    __shared__ __align__(16) float Bs[16 * 128];
    int tid = threadIdx.x;
    int tx = tid & 15, ty = tid >> 4;
    float acc[4][8] = {};
    int am = tid >> 2, akq = tid & 3;
    int bd4 = tid & 31, bli = tid >> 5;

    for (int kt = 0; kt < Dc; kt += 16) {
        float4 av  = *(const float4*)(g_t + (size_t)(r0 + am) * Dc + kt + akq * 4);
        float4 bv0 = *(const float4*)(Wout + (kt + bli) * Dc + bd4 * 4);
        float4 bv1 = *(const float4*)(Wout + (kt + bli + 8) * Dc + bd4 * 4);
        __syncthreads();
        As[(akq * 4 + 0) * 68 + am] = av.x;
        As[(akq * 4 + 1) * 68 + am] = av.y;
        As[(akq * 4 + 2) * 68 + am] = av.z;
        As[(akq * 4 + 3) * 68 + am] = av.w;
        *(float4*)&Bs[bli * 128 + bd4 * 4] = bv0;
        *(float4*)&Bs[(bli + 8) * 128 + bd4 * 4] = bv1;
        __syncthreads();
        #pragma unroll
        for (int kk = 0; kk < 16; ++kk) {
            const float4 a = *(const float4*)&As[kk * 68 + ty * 4];
            const float4 p = *(const float4*)&Bs[kk * 128 + tx * 4];
            const float4 q = *(const float4*)&Bs[kk * 128 + tx * 4 + 64];
            float av4[4] = {a.x, a.y, a.z, a.w};
            float bv8[8] = {p.x, p.y, p.z, p.w, q.x, q.y, q.z, q.w};
            #pragma unroll
            for (int i = 0; i < 4; ++i)
                #pragma unroll
                for (int j = 0; j < 8; ++j)
                    acc[i][j] = fmaf(av4[i], bv8[j], acc[i][j]);
        }
    }
    #pragma unroll
    for (int i = 0; i < 4; ++i) {
        int row = r0 + ty * 4 + i;
        #pragma unroll
        for (int half = 0; half < 2; ++half) {
            float o[4];
            #pragma unroll
            for (int jj = 0; jj < 4; ++jj) {
                int n = tx * 4 + jj + half * 64;
                o[jj] = acc[i][half * 4 + jj] + bout[n];
            }
            *(float4*)(y + (size_t)row * Dc + tx * 4 + half * 64) =
                make_float4(o[0], o[1], o[2], o[3]);
        }
    }
}

extern "C" void kernel_launch(void* const* d_in, const int* in_sizes, int n_in,
                              void* d_out, int out_size) {
    const float* x       = (const float*)d_in[0];
    const float* E       = (const float*)d_in[2];
    const float* EigVals = (const float*)d_in[3];
    const float* bn_g    = (const float*)d_in[4];
    const float* bn_b    = (const float*)d_in[5];
    const float* bn_m    = (const float*)d_in[6];
    const float* bn_v    = (const float*)d_in[7];
    const float* W_in    = (const float*)d_in[8];
    const float* b_in    = (const float*)d_in[9];
    const float* logD    = (const float*)d_in[10];
    const float* Bp      = (const float*)d_in[11];
    const float* Cp      = (const float*)d_in[12];
    const float* logAr   = (const float*)d_in[13];
    const float* Aim     = (const float*)d_in[14];
    const float* Wout    = (const float*)d_in[15];
    const float* bout    = (const float*)d_in[16];
    float* y = (float*)d_out;

    cudaFuncSetAttribute(gemm1_hmma, cudaFuncAttributeMaxDynamicSharedMemorySize, SMEM_BYTES);
    cudaFuncSetAttribute(gemm2_hmma, cudaFuncAttributeMaxDynamicSharedMemorySize, SMEM_BYTES);

    prep_kernel<<<1, 256>>>(bn_g, bn_b, bn_m, bn_v, W_in, b_in, logD, Bp, Cp, logAr, Aim);
    rnorm_kernel<<<ML / 8, 256>>>(E);
    etsplit_kernel<<<dim3(Kc / 32, Lc / 128, Bc), 256>>>(E);
    coef_kernel<<<dim3(Kc / 256, Dc, Bc), 256>>>(EigVals);
    uproj_kernel<<<ML / 64, 512>>>(x);
    gemm1_hmma<<<dim3(Kc / 64, Dc / 64, Bc), 256, SMEM_BYTES>>>();
    gemm2_hmma<<<dim3(Lc / 64, Dc / 64, Bc), 256, SMEM_BYTES>>>();
    outproj_kernel<<<ML / 64, 256>>>(Wout, bout, y);
}

// round 12
// speedup vs baseline: 1.6542x; 1.6542x over previous
#include <cuda_runtime.h>
#include <cuda_bf16.h>
#include <cstdint>
#include <math.h>

#define Bc 8
#define Lc 1024
#define Kc 1024
#define Dc 128
#define Sc 16
#define ML (Bc * Lc)

// ---------------- device scratch ----------------
__device__ float g_W2[Dc * 2 * Dc];
__device__ float g_b2[2 * Dc];
__device__ float g_rnorm[ML];
__device__ float g_t[ML * Dc];
__device__ float g_coefT[Bc * Dc * Kc];          // [b][d][k]
__device__ __nv_bfloat16 d_EhT[Bc * Kc * Lc];    // E^T hi  [b][k][l]
__device__ __nv_bfloat16 d_ElT[Bc * Kc * Lc];    // E^T lo
__device__ __nv_bfloat16 d_u2Th[Bc * Dc * Lc];   // u2^T hi [b][d][l]
__device__ __nv_bfloat16 d_u2Tl[Bc * Dc * Lc];
__device__ __nv_bfloat16 d_VTh[Bc * Dc * Kc];    // V^T hi  [b][d][k]
__device__ __nv_bfloat16 d_VTl[Bc * Dc * Kc];

__device__ __forceinline__ float fsigmoid(float v) { return 1.0f / (1.0f + __expf(-v)); }

__device__ __forceinline__ void split2(float v, __nv_bfloat16& h, __nv_bfloat16& l) {
    h = __float2bfloat16(v);
    l = __float2bfloat16(v - __bfloat162float(h));
}
__device__ __forceinline__ void split4(float4 v, uint2& H, uint2& L) {
    __nv_bfloat162 h01, h23, l01, l23;
    split2(v.x, h01.x, l01.x);
    split2(v.y, h01.y, l01.y);
    split2(v.z, h23.x, l23.x);
    split2(v.w, h23.y, l23.y);
    H.x = *(uint32_t*)&h01; H.y = *(uint32_t*)&h23;
    L.x = *(uint32_t*)&l01; L.y = *(uint32_t*)&l23;
}

__device__ __forceinline__ void mma_bf16(float* c, const uint32_t* a, const uint32_t* b) {
    asm volatile(
        "mma.sync.aligned.m16n8k16.row.col.f32.bf16.bf16.f32 "
        "{%0,%1,%2,%3}, {%4,%5,%6,%7}, {%8,%9}, {%0,%1,%2,%3};"
        : "+f"(c[0]), "+f"(c[1]), "+f"(c[2]), "+f"(c[3])
        : "r"(a[0]), "r"(a[1]), "r"(a[2]), "r"(a[3]), "r"(b[0]), "r"(b[1]));
}

// ================= fused front: prep | rnorm | etsplit | coef =================
// Block roles by flat blockIdx.x:
//   [0, 1024)        rnorm      (8 rows/block)
//   [1024, 3072)     etsplit    (32k x 128l tile)  -> 2048 blocks (32 x 8 x 8)
//   [3072, 7168)     coef       (256 k/block)      -> 4096 blocks (4 x 128 x 8)
//   7168             prep       (BN fold)
__global__ void __launch_bounds__(256) front_kernel(
    const float* __restrict__ E, const float* __restrict__ EigVals,
    const float* __restrict__ bn_g, const float* __restrict__ bn_b,
    const float* __restrict__ bn_m, const float* __restrict__ bn_v,
    const float* __restrict__ W_in, const float* __restrict__ b_in,
    const float* __restrict__ logD, const float* __restrict__ Bp,
    const float* __restrict__ Cp, const float* __restrict__ logAr,
    const float* __restrict__ Aim) {
    __shared__ __align__(16) float FS[32 * 132];   // 16896 B, shared by all roles
    int bid = blockIdx.x;
    int t = threadIdx.x;

    if (bid < 1024) {
        // ---- rnorm: one warp per (b,l) row ----
        int row = bid * 8 + (t >> 5);
        int lane = t & 31;
        const float4* p = (const float4*)(E + (size_t)row * Kc);
        float s = 0.0f;
        #pragma unroll 4
        for (int i = lane; i < Kc / 4; i += 32) {
            float4 v = p[i];
            s += v.x * v.x + v.y * v.y + v.z * v.z + v.w * v.w;
        }
        #pragma unroll
        for (int o = 16; o; o >>= 1) s += __shfl_xor_sync(0xffffffffu, s, o);
        if (lane == 0) g_rnorm[row] = rsqrtf(s);
    } else if (bid < 3072) {
        // ---- etsplit: E[b][l][k] -> EhT/ElT[b][k][l] ----
        int e = bid - 1024;
        int k0 = (e & 31) * 32;
        int l0 = ((e >> 5) & 7) * 128;
        int b = e >> 8;
        int kq = t & 7, lr = t >> 3;
        #pragma unroll
        for (int j = 0; j < 4; ++j) {
            int l = j * 32 + lr;
            float4 v = *(const float4*)(E + ((size_t)(b * Lc + l0 + l)) * Kc + k0 + kq * 4);
            FS[(kq * 4 + 0) * 132 + l] = v.x;
            FS[(kq * 4 + 1) * 132 + l] = v.y;
            FS[(kq * 4 + 2) * 132 + l] = v.z;
            FS[(kq * 4 + 3) * 132 + l] = v.w;
        }
        __syncthreads();
        int k = t >> 3, seg = t & 7;
        __align__(16) __nv_bfloat16 hh[16], ll[16];
        #pragma unroll
        for (int i = 0; i < 4; ++i) {
            float4 v = *(const float4*)&FS[k * 132 + seg * 16 + i * 4];
            split2(v.x, hh[i * 4 + 0], ll[i * 4 + 0]);
            split2(v.y, hh[i * 4 + 1], ll[i * 4 + 1]);
            split2(v.z, hh[i * 4 + 2], ll[i * 4 + 2]);
            split2(v.w, hh[i * 4 + 3], ll[i * 4 + 3]);
        }
        size_t ob = ((size_t)(b * Kc + k0 + k)) * Lc + l0 + seg * 16;
        *(uint4*)(d_EhT + ob) = *(uint4*)hh;
        *(uint4*)(d_EhT + ob + 8) = *(uint4*)(hh + 8);
        *(uint4*)(d_ElT + ob) = *(uint4*)ll;
        *(uint4*)(d_ElT + ob + 8) = *(uint4*)(ll + 8);
    } else if (bid < 7168) {
        // ---- coef: self-contained (recomputes per-d SSM table) ----
        int ce = bid - 3072;
        int kblk = ce & 3;
        int d = (ce >> 2) & 127;
        int b = ce >> 9;
        float* sar = FS;
        float* sm2 = FS + 16;
        float* sw = FS + 32;
        if (t < Sc) {
            int i = d * Sc + t;
            float delta = expf(logD[d]);
            float aR = -expf(logAr[i]);
            float mag = expf(-1e-3f + delta * aR);
            float ang = delta * Aim[i];
            float ar = mag * cosf(ang);
            float ai = mag * sinf(ang);
            sar[t] = ar;
            sm2[t] = ar * ar + ai * ai;
            sw[t] = delta * Bp[i] * Cp[i];
        }
        __syncthreads();
        int kk = kblk * 256 + t;
        float ev = 1.0f - EigVals[b * Kc + kk];
        float ev2 = ev * ev;
        float c = 0.0f;
        #pragma unroll
        for (int s = 0; s < Sc; ++s) {
            float p = ev * sar[s];
            float r = ev2 * sm2[s];
            c = fmaf(sw[s], __fdividef(p - r, 1.0f - 2.0f * p + r), c);
        }
        g_coefT[((size_t)(b * Dc + d)) * Kc + kk] = c;
    } else {
        // ---- prep: fold BN into in_proj ----
        float* sc = FS;
        float* sh = FS + 128;
        if (t < Dc) {
            float s = bn_g[t] * rsqrtf(bn_v[t] + 1e-5f);
            sc[t] = s;
            sh[t] = bn_b[t] - bn_m[t] * s;
        }
        __syncthreads();
        for (int i = t; i < Dc * 2 * Dc; i += 256) g_W2[i] = sc[i / (2 * Dc)] * W_in[i];
        float acc = b_in[t];
        for (int d = 0; d < Dc; ++d) acc = fmaf(sh[d], W_in[d * 2 * Dc + t], acc);
        g_b2[t] = acc;
    }
}

// ---------------- uproj: GLU(in_proj(BN(x))) * rnorm -> u2T hi/lo [b][d][l] ----------------
__global__ void uproj_kernel(const float* __restrict__ x) {
    int r0 = blockIdx.x * 64;
    __shared__ __align__(16) float SU[5188];
    float* As = SU;
    float* Bs = SU + 1088;
    int tid = threadIdx.x;
    int tx = tid & 31, ty = tid >> 5;
    float acc[4][8] = {};
    int am = tid >> 2, akq = tid & 3;
    int bn4 = tid & 63, bli = tid >> 6;

    for (int kt = 0; kt < Dc; kt += 16) {
        float4 av = make_float4(0.f, 0.f, 0.f, 0.f);
        if (tid < 256) av = *(const float4*)(x + (size_t)(r0 + am) * Dc + kt + akq * 4);
        float4 bv0 = *(const float4*)(g_W2 + (kt + bli) * 256 + bn4 * 4);
        float4 bv1 = *(const float4*)(g_W2 + (kt + bli + 8) * 256 + bn4 * 4);
        __syncthreads();
        if (tid < 256) {
            As[(akq * 4 + 0) * 68 + am] = av.x;
            As[(akq * 4 + 1) * 68 + am] = av.y;
            As[(akq * 4 + 2) * 68 + am] = av.z;
            As[(akq * 4 + 3) * 68 + am] = av.w;
        }
        *(float4*)&Bs[bli * 256 + bn4 * 4] = bv0;
        *(float4*)&Bs[(bli + 8) * 256 + bn4 * 4] = bv1;
        __syncthreads();
        #pragma unroll
        for (int kk = 0; kk < 16; ++kk) {
            const float4 a = *(const float4*)&As[kk * 68 + ty * 4];
            const float4 p = *(const float4*)&Bs[kk * 256 + tx * 4];
            const float4 q = *(const float4*)&Bs[kk * 256 + tx * 4 + 128];
            float av4[4] = {a.x, a.y, a.z, a.w};
            float bv8[8] = {p.x, p.y, p.z, p.w, q.x, q.y, q.z, q.w};
            #pragma unroll
            for (int i = 0; i < 4; ++i)
                #pragma unroll
                for (int j = 0; j < 8; ++j)
                    acc[i][j] = fmaf(av4[i], bv8[j], acc[i][j]);
        }
    }
    int b = r0 >> 10, l0 = r0 & 1023;
    #pragma unroll
    for (int h = 0; h < 2; ++h) {
        __syncthreads();
        if ((tx >> 4) == h) {
            #pragma unroll
            for (int i = 0; i < 4; ++i) {
                int row = r0 + ty * 4 + i;
                float rn = g_rnorm[row];
                int l = ty * 4 + i;
                #pragma unroll
                for (int jj = 0; jj < 4; ++jj) {
                    int n = tx * 4 + jj;
                    float lo = acc[i][jj] + g_b2[n];
                    float hi = acc[i][jj + 4] + g_b2[n + 128];
                    SU[(n - h * 64) * 65 + l] = lo * hi * fsigmoid(hi) * rn;
                }
            }
        }
        __syncthreads();
        int dd = tid >> 3, sg = tid & 7;
        __align__(16) __nv_bfloat16 hh[8], ll[8];
        #pragma unroll
        for (int q = 0; q < 8; ++q) split2(SU[dd * 65 + sg * 8 + q], hh[q], ll[q]);
        size_t ob = ((size_t)(b * Dc + h * 64 + dd)) * Lc + l0 + sg * 8;
        *(uint4*)(d_u2Th + ob) = *(uint4*)hh;
        *(uint4*)(d_u2Tl + ob) = *(uint4*)ll;
    }
}

// ---------------- HMMA tile machinery (R8-exact: 64x128 tile, reg double-buffer) ----------------
#define RS 40
#define ASZ (64 * RS)
#define BSZ (128 * RS)
#define STG_H (2 * ASZ + 2 * BSZ)   // 15360 halfs = 30720 B per stage
#define SMEM_BYTES (2 * STG_H * 2)  // 61440

__device__ __forceinline__ void hmma_compute(const __nv_bfloat16* s, int wid, int lane,
                                             float C[2][4][4]) {
    const __nv_bfloat16* sAh = s;
    const __nv_bfloat16* sAl = s + ASZ;
    const __nv_bfloat16* sBh = s + 2 * ASZ;
    const __nv_bfloat16* sBl = s + 2 * ASZ + BSZ;
    int wm = wid & 1, wn = wid >> 1;
    int lr = lane >> 2, lc = (lane & 3) * 2;
    #pragma unroll
    for (int ks = 0; ks < 2; ++ks) {
        int acol = ks * 16 + lc;
        uint32_t ah[2][4], al[2][4], bh[4][2], bl[4][2];
        #pragma unroll
        for (int mi = 0; mi < 2; ++mi) {
            int rb = wm * 32 + mi * 16 + lr;
            ah[mi][0] = *(const uint32_t*)(sAh + rb * RS + acol);
            ah[mi][1] = *(const uint32_t*)(sAh + (rb + 8) * RS + acol);
            ah[mi][2] = *(const uint32_t*)(sAh + rb * RS + acol + 8);
            ah[mi][3] = *(const uint32_t*)(sAh + (rb + 8) * RS + acol + 8);
            al[mi][0] = *(const uint32_t*)(sAl + rb * RS + acol);
            al[mi][1] = *(const uint32_t*)(sAl + (rb + 8) * RS + acol);
            al[mi][2] = *(const uint32_t*)(sAl + rb * RS + acol + 8);
            al[mi][3] = *(const uint32_t*)(sAl + (rb + 8) * RS + acol + 8);
        }
        #pragma unroll
        for (int ni = 0; ni < 4; ++ni) {
            int nr = wn * 32 + ni * 8 + lr;
            bh[ni][0] = *(const uint32_t*)(sBh + nr * RS + acol);
            bh[ni][1] = *(const uint32_t*)(sBh + nr * RS + acol + 8);
            bl[ni][0] = *(const uint32_t*)(sBl + nr * RS + acol);
            bl[ni][1] = *(const uint32_t*)(sBl + nr * RS + acol + 8);
        }
        #pragma unroll
        for (int mi = 0; mi < 2; ++mi)
            #pragma unroll
            for (int ni = 0; ni < 4; ++ni) {
                mma_bf16(C[mi][ni], ah[mi], bh[ni]);
                mma_bf16(C[mi][ni], ah[mi], bl[ni]);
                mma_bf16(C[mi][ni], al[mi], bh[ni]);
            }
    }
}

struct G1R { uint4 ah, al, bh0, bh1, bl0, bl1; };
__device__ __forceinline__ void g1_load(G1R& r, const __nv_bfloat16* Ah, const __nv_bfloat16* Al,
                                        const __nv_bfloat16* Bh, const __nv_bfloat16* Bl,
                                        int tid, int l0) {
    int ar = tid >> 2, as = tid & 3;
    size_t ao = (size_t)ar * Lc + l0 + as * 8;
    r.ah = *(const uint4*)(Ah + ao);
    r.al = *(const uint4*)(Al + ao);
    size_t bo0 = (size_t)ar * Lc + l0 + as * 8;
    size_t bo1 = (size_t)(ar + 64) * Lc + l0 + as * 8;
    r.bh0 = *(const uint4*)(Bh + bo0);
    r.bh1 = *(const uint4*)(Bh + bo1);
    r.bl0 = *(const uint4*)(Bl + bo0);
    r.bl1 = *(const uint4*)(Bl + bo1);
}
__device__ __forceinline__ void g1_store(__nv_bfloat16* s, int tid, const G1R& r) {
    int ar = tid >> 2, as = tid & 3;
    *(uint4*)(s + ar * RS + as * 8) = r.ah;
    *(uint4*)(s + ASZ + ar * RS + as * 8) = r.al;
    *(uint4*)(s + 2 * ASZ + ar * RS + as * 8) = r.bh0;
    *(uint4*)(s + 2 * ASZ + (ar + 64) * RS + as * 8) = r.bh1;
    *(uint4*)(s + 2 * ASZ + BSZ + ar * RS + as * 8) = r.bl0;
    *(uint4*)(s + 2 * ASZ + BSZ + (ar + 64) * RS + as * 8) = r.bl1;
}

// GEMM1: D[k,d] = sum_l EhT[k][l]*u2T[d][l]; epilogue *coef -> VT hi/lo
__global__ void __launch_bounds__(256, 1) gemm1_hmma() {
    extern __shared__ __align__(16) char smraw[];
    __nv_bfloat16* sm = (__nv_bfloat16*)smraw;
    int tid = threadIdx.x, wid = tid >> 5, lane = tid & 31;
    int b = blockIdx.y, k0 = blockIdx.x * 64;

    const __nv_bfloat16* Ah = d_EhT + ((size_t)(b * Kc + k0)) * Lc;
    const __nv_bfloat16* Al = d_ElT + ((size_t)(b * Kc + k0)) * Lc;
    const __nv_bfloat16* Bh = d_u2Th + (size_t)(b * Dc) * Lc;
    const __nv_bfloat16* Bl = d_u2Tl + (size_t)(b * Dc) * Lc;

    float C[2][4][4] = {};
    G1R r;
    g1_load(r, Ah, Al, Bh, Bl, tid, 0);
    g1_store(sm, tid, r);
    __syncthreads();
    g1_load(r, Ah, Al, Bh, Bl, tid, 32);
    for (int c = 0; c < 32; ++c) {
        hmma_compute(sm + (c & 1) * STG_H, wid, lane, C);
        if (c + 1 < 32) {
            __syncthreads();
            g1_store(sm + ((c + 1) & 1) * STG_H, tid, r);
            if (c + 2 < 32) g1_load(r, Ah, Al, Bh, Bl, tid, (c + 2) * 32);
            __syncthreads();
        }
    }
    __syncthreads();
    float* Cst = (float*)smraw;  // 64 x 133
    {
        int wm = wid & 1, wn = wid >> 1;
        int lr = lane >> 2, lc = (lane & 3) * 2;
        #pragma unroll
        for (int mi = 0; mi < 2; ++mi)
            #pragma unroll
            for (int ni = 0; ni < 4; ++ni) {
                int rr = wm * 32 + mi * 16 + lr;
                int cc = wn * 32 + ni * 8 + lc;
                Cst[rr * 133 + cc] = C[mi][ni][0];
                Cst[rr * 133 + cc + 1] = C[mi][ni][1];
                Cst[(rr + 8) * 133 + cc] = C[mi][ni][2];
                Cst[(rr + 8) * 133 + cc + 1] = C[mi][ni][3];
            }
    }
    __syncthreads();
    #pragma unroll
    for (int rr = 0; rr < 16; ++rr) {
        int d = wid * 16 + rr;
        const float* cf = g_coefT + (size_t)(b * Dc + d) * Kc + k0;
        __nv_bfloat16* vh = d_VTh + (size_t)(b * Dc + d) * Kc + k0;
        __nv_bfloat16* vl = d_VTl + (size_t)(b * Dc + d) * Kc + k0;
        #pragma unroll
        for (int it = 0; it < 2; ++it) {
            int k = it * 32 + lane;
            float v = Cst[k * 133 + d] * cf[k];
            __nv_bfloat16 h, l;
            split2(v, h, l);
            vh[k] = h;
            vl[k] = l;
        }
    }
}

// GEMM2: D[l,d] = sum_k E[l][k]*VT[d][k]; silu*rnorm -> g_t
struct G2R { float4 e0, e1; uint4 bh0, bh1, bl0, bl1; };
__device__ __forceinline__ void g2_load(G2R& r, const float* Eb, const __nv_bfloat16* Bh,
                                        const __nv_bfloat16* Bl, int tid, int kc0) {
    int r0 = tid >> 3, s0 = tid & 7;
    r.e0 = *(const float4*)(Eb + (size_t)r0 * Kc + kc0 + s0 * 4);
    r.e1 = *(const float4*)(Eb + (size_t)(r0 + 32) * Kc + kc0 + s0 * 4);
    int br = tid >> 2, bs = tid & 3;
    size_t bo0 = (size_t)br * Kc + kc0 + bs * 8;
    size_t bo1 = (size_t)(br + 64) * Kc + kc0 + bs * 8;
    r.bh0 = *(const uint4*)(Bh + bo0);
    r.bh1 = *(const uint4*)(Bh + bo1);
    r.bl0 = *(const uint4*)(Bl + bo0);
    r.bl1 = *(const uint4*)(Bl + bo1);
}
__device__ __forceinline__ void g2_store(__nv_bfloat16* s, int tid, const G2R& r) {
    int r0 = tid >> 3, s0 = tid & 7;
    uint2 H, L;
    split4(r.e0, H, L);
    *(uint2*)(s + r0 * RS + s0 * 4) = H;
    *(uint2*)(s + ASZ + r0 * RS + s0 * 4) = L;
    split4(r.e1, H, L);
    *(uint2*)(s + (r0 + 32) * RS + s0 * 4) = H;
    *(uint2*)(s + ASZ + (r0 + 32) * RS + s0 * 4) = L;
    int br = tid >> 2, bs = tid & 3;
    *(uint4*)(s + 2 * ASZ + br * RS + bs * 8) = r.bh0;
    *(uint4*)(s + 2 * ASZ + (br + 64) * RS + bs * 8) = r.bh1;
    *(uint4*)(s + 2 * ASZ + BSZ + br * RS + bs * 8) = r.bl0;
    *(uint4*)(s + 2 * ASZ + BSZ + (br + 64) * RS + bs * 8) = r.bl1;
}

__global__ void __launch_bounds__(256, 1) gemm2_hmma(const float* __restrict__ E) {
    extern __shared__ __align__(16) char smraw[];
    __nv_bfloat16* sm = (__nv_bfloat16*)smraw;
    int tid = threadIdx.x, wid = tid >> 5, lane = tid & 31;
    int b = blockIdx.y, l0 = blockIdx.x * 64;

    const float* Eb = E + ((size_t)(b * Lc + l0)) * Kc;
    const __nv_bfloat16* Bh = d_VTh + (size_t)(b * Dc) * Kc;
    const __nv_bfloat16* Bl = d_VTl + (size_t)(b * Dc) * Kc;

    float C[2][4][4] = {};
    G2R r;
    g2_load(r, Eb, Bh, Bl, tid, 0);
    g2_store(sm, tid, r);
    __syncthreads();
    g2_load(r, Eb, Bh, Bl, tid, 32);
    for (int c = 0; c < 32; ++c) {
        hmma_compute(sm + (c & 1) * STG_H, wid, lane, C);
        if (c + 1 < 32) {
            __syncthreads();
            g2_store(sm + ((c + 1) & 1) * STG_H, tid, r);
            if (c + 2 < 32) g2_load(r, Eb, Bh, Bl, tid, (c + 2) * 32);
            __syncthreads();
        }
    }
    int wm = wid & 1, wn = wid >> 1;
    int lr = lane >> 2, lc = (lane & 3) * 2;
    #pragma unroll
    for (int mi = 0; mi < 2; ++mi) {
        int lg0 = l0 + wm * 32 + mi * 16 + lr;
        float rn0 = g_rnorm[b * Lc + lg0];
        float rn1 = g_rnorm[b * Lc + lg0 + 8];
        float* t0 = g_t + ((size_t)(b * Lc + lg0)) * Dc;
        float* t1 = t0 + 8 * Dc;
        #pragma unroll
        for (int ni = 0; ni < 4; ++ni) {
            int d = wn * 32 + ni * 8 + lc;
            float v0 = C[mi][ni][0] * rn0, v1 = C[mi][ni][1] * rn0;
            float v2 = C[mi][ni][2] * rn1, v3 = C[mi][ni][3] * rn1;
            *(float2*)(t0 + d) = make_float2(v0 * fsigmoid(v0), v1 * fsigmoid(v1));
            *(float2*)(t1 + d) = make_float2(v2 * fsigmoid(v2), v3 * fsigmoid(v3));
        }
    }
}

// ---------------- out_proj ----------------
__global__ void outproj_kernel(const float* __restrict__ Wout, const float* __restrict__ bout,
                               float* __restrict__ y) {
    int r0 = blockIdx.x * 64;
    __shared__ __align__(16) float As[16 * 68];
    __shared__ __align__(16) float Bs[16 * 128];
    int tid = threadIdx.x;
    int tx = tid & 15, ty = tid >> 4;
    float acc[4][8] = {};
    int am = tid >> 2, akq = tid & 3;
    int bd4 = tid & 31, bli = tid >> 5;

    for (int kt = 0; kt < Dc; kt += 16) {
        float4 av  = *(const float4*)(g_t + (size_t)(r0 + am) * Dc + kt + akq * 4);
        float4 bv0 = *(const float4*)(Wout + (kt + bli) * Dc + bd4 * 4);
        float4 bv1 = *(const float4*)(Wout + (kt + bli + 8) * Dc + bd4 * 4);
        __syncthreads();
        As[(akq * 4 + 0) * 68 + am] = av.x;
        As[(akq * 4 + 1) * 68 + am] = av.y;
        As[(akq * 4 + 2) * 68 + am] = av.z;
        As[(akq * 4 + 3) * 68 + am] = av.w;
        *(float4*)&Bs[bli * 128 + bd4 * 4] = bv0;
        *(float4*)&Bs[(bli + 8) * 128 + bd4 * 4] = bv1;
        __syncthreads();
        #pragma unroll
        for (int kk = 0; kk < 16; ++kk) {
            const float4 a = *(const float4*)&As[kk * 68 + ty * 4];
            const float4 p = *(const float4*)&Bs[kk * 128 + tx * 4];
            const float4 q = *(const float4*)&Bs[kk * 128 + tx * 4 + 64];
            float av4[4] = {a.x, a.y, a.z, a.w};
            float bv8[8] = {p.x, p.y, p.z, p.w, q.x, q.y, q.z, q.w};
            #pragma unroll
            for (int i = 0; i < 4; ++i)
                #pragma unroll
                for (int j = 0; j < 8; ++j)
                    acc[i][j] = fmaf(av4[i], bv8[j], acc[i][j]);
        }
    }
    #pragma unroll
    for (int i = 0; i < 4; ++i) {
        int row = r0 + ty * 4 + i;
        #pragma unroll
        for (int half = 0; half < 2; ++half) {
            float o[4];
            #pragma unroll
            for (int jj = 0; jj < 4; ++jj) {
                int n = tx * 4 + jj + half * 64;
                o[jj] = acc[i][half * 4 + jj] + bout[n];
            }
            *(float4*)(y + (size_t)row * Dc + tx * 4 + half * 64) =
                make_float4(o[0], o[1], o[2], o[3]);
        }
    }
}

extern "C" void kernel_launch(void* const* d_in, const int* in_sizes, int n_in,
                              void* d_out, int out_size) {
    const float* x       = (const float*)d_in[0];
    const float* E       = (const float*)d_in[2];
    const float* EigVals = (const float*)d_in[3];
    const float* bn_g    = (const float*)d_in[4];
    const float* bn_b    = (const float*)d_in[5];
    const float* bn_m    = (const float*)d_in[6];
    const float* bn_v    = (const float*)d_in[7];
    const float* W_in    = (const float*)d_in[8];
    const float* b_in    = (const float*)d_in[9];
    const float* logD    = (const float*)d_in[10];
    const float* Bp      = (const float*)d_in[11];
    const float* Cp      = (const float*)d_in[12];
    const float* logAr   = (const float*)d_in[13];
    const float* Aim     = (const float*)d_in[14];
    const float* Wout    = (const float*)d_in[15];
    const float* bout    = (const float*)d_in[16];
    float* y = (float*)d_out;

    cudaFuncSetAttribute(gemm1_hmma, cudaFuncAttributeMaxDynamicSharedMemorySize, SMEM_BYTES);
    cudaFuncSetAttribute(gemm2_hmma, cudaFuncAttributeMaxDynamicSharedMemorySize, SMEM_BYTES);

    front_kernel<<<7169, 256>>>(E, EigVals, bn_g, bn_b, bn_m, bn_v, W_in, b_in,
                                logD, Bp, Cp, logAr, Aim);
    uproj_kernel<<<ML / 64, 512>>>(x);
    gemm1_hmma<<<dim3(Kc / 64, Bc), 256, SMEM_BYTES>>>();
    gemm2_hmma<<<dim3(Lc / 64, Bc), 256, SMEM_BYTES>>>(E);
    outproj_kernel<<<ML / 64, 256>>>(Wout, bout, y);
}

// round 13
// speedup vs baseline: 1.6986x; 1.0269x over previous
#include <cuda_runtime.h>
#include <cuda_bf16.h>
#include <cstdint>
#include <math.h>

#define Bc 8
#define Lc 1024
#define Kc 1024
#define Dc 128
#define Sc 16
#define ML (Bc * Lc)

// ---------------- device scratch ----------------
__device__ float g_W2[Dc * 2 * Dc];
__device__ float g_b2[2 * Dc];
__device__ float g_rnorm[ML];
__device__ float g_t[ML * Dc];
__device__ float g_coefT[Bc * Dc * Kc];          // [b][d][k]
__device__ __nv_bfloat16 d_EhT[Bc * Kc * Lc];    // E^T hi  [b][k][l]
__device__ __nv_bfloat16 d_ElT[Bc * Kc * Lc];    // E^T lo
__device__ __nv_bfloat16 d_Eh[Bc * Lc * Kc];     // E hi    [b][l][k]
__device__ __nv_bfloat16 d_El[Bc * Lc * Kc];     // E lo
__device__ __nv_bfloat16 d_u2Th[Bc * Dc * Lc];   // u2^T hi [b][d][l]
__device__ __nv_bfloat16 d_u2Tl[Bc * Dc * Lc];
__device__ __nv_bfloat16 d_VTh[Bc * Dc * Kc];    // V^T hi  [b][d][k]
__device__ __nv_bfloat16 d_VTl[Bc * Dc * Kc];

__device__ __forceinline__ float fsigmoid(float v) { return 1.0f / (1.0f + __expf(-v)); }

__device__ __forceinline__ void split2(float v, __nv_bfloat16& h, __nv_bfloat16& l) {
    h = __float2bfloat16(v);
    l = __float2bfloat16(v - __bfloat162float(h));
}
__device__ __forceinline__ void split4(float4 v, uint2& H, uint2& L) {
    __nv_bfloat162 h01, h23, l01, l23;
    split2(v.x, h01.x, l01.x);
    split2(v.y, h01.y, l01.y);
    split2(v.z, h23.x, l23.x);
    split2(v.w, h23.y, l23.y);
    H.x = *(uint32_t*)&h01; H.y = *(uint32_t*)&h23;
    L.x = *(uint32_t*)&l01; L.y = *(uint32_t*)&l23;
}

__device__ __forceinline__ void mma_bf16(float* c, const uint32_t* a, const uint32_t* b) {
    asm volatile(
        "mma.sync.aligned.m16n8k16.row.col.f32.bf16.bf16.f32 "
        "{%0,%1,%2,%3}, {%4,%5,%6,%7}, {%8,%9}, {%0,%1,%2,%3};"
        : "+f"(c[0]), "+f"(c[1]), "+f"(c[2]), "+f"(c[3])
        : "r"(a[0]), "r"(a[1]), "r"(a[2]), "r"(a[3]), "r"(b[0]), "r"(b[1]));
}

__device__ __forceinline__ void cp16(uint32_t dst, const void* src) {
    asm volatile("cp.async.cg.shared.global [%0], [%1], 16;" :: "r"(dst), "l"(src));
}
#define CP_COMMIT() asm volatile("cp.async.commit_group;" ::: "memory")
template <int N>
__device__ __forceinline__ void cp_wait() {
    asm volatile("cp.async.wait_group %0;" :: "n"(N) : "memory");
}

// ================= fused front: prep | rnorm | etsplit | coef =================
__global__ void __launch_bounds__(256) front_kernel(
    const float* __restrict__ E, const float* __restrict__ EigVals,
    const float* __restrict__ bn_g, const float* __restrict__ bn_b,
    const float* __restrict__ bn_m, const float* __restrict__ bn_v,
    const float* __restrict__ W_in, const float* __restrict__ b_in,
    const float* __restrict__ logD, const float* __restrict__ Bp,
    const float* __restrict__ Cp, const float* __restrict__ logAr,
    const float* __restrict__ Aim) {
    __shared__ __align__(16) float FS[32 * 132];
    int bid = blockIdx.x;
    int t = threadIdx.x;

    if (bid < 1024) {
        // ---- rnorm ----
        int row = bid * 8 + (t >> 5);
        int lane = t & 31;
        const float4* p = (const float4*)(E + (size_t)row * Kc);
        float s = 0.0f;
        #pragma unroll 4
        for (int i = lane; i < Kc / 4; i += 32) {
            float4 v = p[i];
            s += v.x * v.x + v.y * v.y + v.z * v.z + v.w * v.w;
        }
        #pragma unroll
        for (int o = 16; o; o >>= 1) s += __shfl_xor_sync(0xffffffffu, s, o);
        if (lane == 0) g_rnorm[row] = rsqrtf(s);
    } else if (bid < 3072) {
        // ---- etsplit: E -> Eh/El (straight) + EhT/ElT (transposed) ----
        int e = bid - 1024;
        int k0 = (e & 31) * 32;
        int l0 = ((e >> 5) & 7) * 128;
        int b = e >> 8;
        int kq = t & 7, lr = t >> 3;
        #pragma unroll
        for (int j = 0; j < 4; ++j) {
            int l = j * 32 + lr;
            size_t go = ((size_t)(b * Lc + l0 + l)) * Kc + k0 + kq * 4;
            float4 v = *(const float4*)(E + go);
            uint2 H, L;
            split4(v, H, L);
            *(uint2*)(d_Eh + go) = H;
            *(uint2*)(d_El + go) = L;
            FS[(kq * 4 + 0) * 132 + l] = v.x;
            FS[(kq * 4 + 1) * 132 + l] = v.y;
            FS[(kq * 4 + 2) * 132 + l] = v.z;
            FS[(kq * 4 + 3) * 132 + l] = v.w;
        }
        __syncthreads();
        int k = t >> 3, seg = t & 7;
        __align__(16) __nv_bfloat16 hh[16], ll[16];
        #pragma unroll
        for (int i = 0; i < 4; ++i) {
            float4 v = *(const float4*)&FS[k * 132 + seg * 16 + i * 4];
            split2(v.x, hh[i * 4 + 0], ll[i * 4 + 0]);
            split2(v.y, hh[i * 4 + 1], ll[i * 4 + 1]);
            split2(v.z, hh[i * 4 + 2], ll[i * 4 + 2]);
            split2(v.w, hh[i * 4 + 3], ll[i * 4 + 3]);
        }
        size_t ob = ((size_t)(b * Kc + k0 + k)) * Lc + l0 + seg * 16;
        *(uint4*)(d_EhT + ob) = *(uint4*)hh;
        *(uint4*)(d_EhT + ob + 8) = *(uint4*)(hh + 8);
        *(uint4*)(d_ElT + ob) = *(uint4*)ll;
        *(uint4*)(d_ElT + ob + 8) = *(uint4*)(ll + 8);
    } else if (bid < 7168) {
        // ---- coef ----
        int ce = bid - 3072;
        int kblk = ce & 3;
        int d = (ce >> 2) & 127;
        int b = ce >> 9;
        float* sar = FS;
        float* sm2 = FS + 16;
        float* sw = FS + 32;
        if (t < Sc) {
            int i = d * Sc + t;
            float delta = expf(logD[d]);
            float aR = -expf(logAr[i]);
            float mag = expf(-1e-3f + delta * aR);
            float ang = delta * Aim[i];
            float ar = mag * cosf(ang);
            float ai = mag * sinf(ang);
            sar[t] = ar;
            sm2[t] = ar * ar + ai * ai;
            sw[t] = delta * Bp[i] * Cp[i];
        }
        __syncthreads();
        int kk = kblk * 256 + t;
        float ev = 1.0f - EigVals[b * Kc + kk];
        float ev2 = ev * ev;
        float c = 0.0f;
        #pragma unroll
        for (int s = 0; s < Sc; ++s) {
            float p = ev * sar[s];
            float r = ev2 * sm2[s];
            c = fmaf(sw[s], __fdividef(p - r, 1.0f - 2.0f * p + r), c);
        }
        g_coefT[((size_t)(b * Dc + d)) * Kc + kk] = c;
    } else {
        // ---- prep ----
        float* sc = FS;
        float* sh = FS + 128;
        if (t < Dc) {
            float s = bn_g[t] * rsqrtf(bn_v[t] + 1e-5f);
            sc[t] = s;
            sh[t] = bn_b[t] - bn_m[t] * s;
        }
        __syncthreads();
        for (int i = t; i < Dc * 2 * Dc; i += 256) g_W2[i] = sc[i / (2 * Dc)] * W_in[i];
        float acc = b_in[t];
        for (int d = 0; d < Dc; ++d) acc = fmaf(sh[d], W_in[d * 2 * Dc + t], acc);
        g_b2[t] = acc;
    }
}

// ---------------- uproj ----------------
__global__ void uproj_kernel(const float* __restrict__ x) {
    int r0 = blockIdx.x * 64;
    __shared__ __align__(16) float SU[5188];
    float* As = SU;
    float* Bs = SU + 1088;
    int tid = threadIdx.x;
    int tx = tid & 31, ty = tid >> 5;
    float acc[4][8] = {};
    int am = tid >> 2, akq = tid & 3;
    int bn4 = tid & 63, bli = tid >> 6;

    for (int kt = 0; kt < Dc; kt += 16) {
        float4 av = make_float4(0.f, 0.f, 0.f, 0.f);
        if (tid < 256) av = *(const float4*)(x + (size_t)(r0 + am) * Dc + kt + akq * 4);
        float4 bv0 = *(const float4*)(g_W2 + (kt + bli) * 256 + bn4 * 4);
        float4 bv1 = *(const float4*)(g_W2 + (kt + bli + 8) * 256 + bn4 * 4);
        __syncthreads();
        if (tid < 256) {
            As[(akq * 4 + 0) * 68 + am] = av.x;
            As[(akq * 4 + 1) * 68 + am] = av.y;
            As[(akq * 4 + 2) * 68 + am] = av.z;
            As[(akq * 4 + 3) * 68 + am] = av.w;
        }
        *(float4*)&Bs[bli * 256 + bn4 * 4] = bv0;
        *(float4*)&Bs[(bli + 8) * 256 + bn4 * 4] = bv1;
        __syncthreads();
        #pragma unroll
        for (int kk = 0; kk < 16; ++kk) {
            const float4 a = *(const float4*)&As[kk * 68 + ty * 4];
            const float4 p = *(const float4*)&Bs[kk * 256 + tx * 4];
            const float4 q = *(const float4*)&Bs[kk * 256 + tx * 4 + 128];
            float av4[4] = {a.x, a.y, a.z, a.w};
            float bv8[8] = {p.x, p.y, p.z, p.w, q.x, q.y, q.z, q.w};
            #pragma unroll
            for (int i = 0; i < 4; ++i)
                #pragma unroll
                for (int j = 0; j < 8; ++j)
                    acc[i][j] = fmaf(av4[i], bv8[j], acc[i][j]);
        }
    }
    int b = r0 >> 10, l0 = r0 & 1023;
    #pragma unroll
    for (int h = 0; h < 2; ++h) {
        __syncthreads();
        if ((tx >> 4) == h) {
            #pragma unroll
            for (int i = 0; i < 4; ++i) {
                int row = r0 + ty * 4 + i;
                float rn = g_rnorm[row];
                int l = ty * 4 + i;
                #pragma unroll
                for (int jj = 0; jj < 4; ++jj) {
                    int n = tx * 4 + jj;
                    float lo = acc[i][jj] + g_b2[n];
                    float hi = acc[i][jj + 4] + g_b2[n + 128];
                    SU[(n - h * 64) * 65 + l] = lo * hi * fsigmoid(hi) * rn;
                }
            }
        }
        __syncthreads();
        int dd = tid >> 3, sg = tid & 7;
        __align__(16) __nv_bfloat16 hh[8], ll[8];
        #pragma unroll
        for (int q = 0; q < 8; ++q) split2(SU[dd * 65 + sg * 8 + q], hh[q], ll[q]);
        size_t ob = ((size_t)(b * Dc + h * 64 + dd)) * Lc + l0 + sg * 8;
        *(uint4*)(d_u2Th + ob) = *(uint4*)hh;
        *(uint4*)(d_u2Tl + ob) = *(uint4*)ll;
    }
}

// ---------------- HMMA: 64x128 tile, k-chunk 32, 4-stage cp.async ----------------
#define RS 40
#define ASZ (64 * RS)               // 2560 halfs
#define BSZ (128 * RS)              // 5120 halfs
#define AhB 0
#define AlB (ASZ * 2)               // 5120 B
#define BhB (2 * ASZ * 2)           // 10240 B
#define BlB ((2 * ASZ + BSZ) * 2)   // 20480 B
#define STGB ((2 * ASZ + 2 * BSZ) * 2)  // 30720 B
#define NSTG 4
#define SMEM_BYTES (NSTG * STGB)    // 122880

__device__ __forceinline__ void hmma_compute(const __nv_bfloat16* s, int wid, int lane,
                                             float C[2][4][4]) {
    const __nv_bfloat16* sAh = s;
    const __nv_bfloat16* sAl = s + ASZ;
    const __nv_bfloat16* sBh = s + 2 * ASZ;
    const __nv_bfloat16* sBl = s + 2 * ASZ + BSZ;
    int wm = wid & 1, wn = wid >> 1;
    int lr = lane >> 2, lc = (lane & 3) * 2;
    #pragma unroll
    for (int ks = 0; ks < 2; ++ks) {
        int acol = ks * 16 + lc;
        uint32_t ah[2][4], al[2][4], bh[4][2], bl[4][2];
        #pragma unroll
        for (int mi = 0; mi < 2; ++mi) {
            int rb = wm * 32 + mi * 16 + lr;
            ah[mi][0] = *(const uint32_t*)(sAh + rb * RS + acol);
            ah[mi][1] = *(const uint32_t*)(sAh + (rb + 8) * RS + acol);
            ah[mi][2] = *(const uint32_t*)(sAh + rb * RS + acol + 8);
            ah[mi][3] = *(const uint32_t*)(sAh + (rb + 8) * RS + acol + 8);
            al[mi][0] = *(const uint32_t*)(sAl + rb * RS + acol);
            al[mi][1] = *(const uint32_t*)(sAl + (rb + 8) * RS + acol);
            al[mi][2] = *(const uint32_t*)(sAl + rb * RS + acol + 8);
            al[mi][3] = *(const uint32_t*)(sAl + (rb + 8) * RS + acol + 8);
        }
        #pragma unroll
        for (int ni = 0; ni < 4; ++ni) {
            int nr = wn * 32 + ni * 8 + lr;
            bh[ni][0] = *(const uint32_t*)(sBh + nr * RS + acol);
            bh[ni][1] = *(const uint32_t*)(sBh + nr * RS + acol + 8);
            bl[ni][0] = *(const uint32_t*)(sBl + nr * RS + acol);
            bl[ni][1] = *(const uint32_t*)(sBl + nr * RS + acol + 8);
        }
        #pragma unroll
        for (int mi = 0; mi < 2; ++mi)
            #pragma unroll
            for (int ni = 0; ni < 4; ++ni) {
                mma_bf16(C[mi][ni], ah[mi], bh[ni]);
                mma_bf16(C[mi][ni], ah[mi], bl[ni]);
                mma_bf16(C[mi][ni], al[mi], bh[ni]);
            }
    }
}

// All operands K-contiguous with lead dim 1024. 6 cp16 per thread per stage.
__device__ __forceinline__ void tn_issue(uint32_t sb, const __nv_bfloat16* Ah,
                                         const __nv_bfloat16* Al, const __nv_bfloat16* Bh,
                                         const __nv_bfloat16* Bl, int tid, int kc0) {
    int row = tid >> 2, seg = tid & 3;
    uint32_t off0 = (uint32_t)(row * RS + seg * 8) * 2;
    uint32_t off1 = (uint32_t)((row + 64) * RS + seg * 8) * 2;
    size_t go0 = (size_t)row * 1024 + kc0 + seg * 8;
    size_t go1 = (size_t)(row + 64) * 1024 + kc0 + seg * 8;
    cp16(sb + AhB + off0, Ah + go0);
    cp16(sb + AlB + off0, Al + go0);
    cp16(sb + BhB + off0, Bh + go0);
    cp16(sb + BhB + off1, Bh + go1);
    cp16(sb + BlB + off0, Bl + go0);
    cp16(sb + BlB + off1, Bl + go1);
}

#define TN_MAINLOOP(Ah, Al, Bh, Bl)                                                   \
    {                                                                                 \
        tn_issue(sb, Ah, Al, Bh, Bl, tid, 0);                                         \
        CP_COMMIT();                                                                  \
        tn_issue(sb + STGB, Ah, Al, Bh, Bl, tid, 32);                                 \
        CP_COMMIT();                                                                  \
        tn_issue(sb + 2 * STGB, Ah, Al, Bh, Bl, tid, 64);                             \
        CP_COMMIT();                                                                  \
        for (int c = 0; c < 32; ++c) {                                                \
            if (c < 30) cp_wait<2>();                                                 \
            else if (c == 30) cp_wait<1>();                                           \
            else cp_wait<0>();                                                        \
            __syncthreads();                                                          \
            hmma_compute((const __nv_bfloat16*)(smraw + (c & 3) * STGB), wid, lane, C); \
            if (c + 3 < 32) {                                                         \
                tn_issue(sb + ((c + 3) & 3) * STGB, Ah, Al, Bh, Bl, tid, (c + 3) * 32); \
                CP_COMMIT();                                                          \
            }                                                                         \
        }                                                                             \
    }

// GEMM1: D[k,d] = sum_l EhT[k][l]*u2T[d][l]; epilogue *coef -> VT hi/lo
__global__ void __launch_bounds__(256, 1) gemm1_hmma() {
    extern __shared__ __align__(16) char smraw[];
    uint32_t sb = (uint32_t)__cvta_generic_to_shared(smraw);
    int tid = threadIdx.x, wid = tid >> 5, lane = tid & 31;
    int b = blockIdx.y, k0 = blockIdx.x * 64;

    const __nv_bfloat16* Ah = d_EhT + ((size_t)(b * Kc + k0)) * Lc;
    const __nv_bfloat16* Al = d_ElT + ((size_t)(b * Kc + k0)) * Lc;
    const __nv_bfloat16* Bh = d_u2Th + (size_t)(b * Dc) * Lc;
    const __nv_bfloat16* Bl = d_u2Tl + (size_t)(b * Dc) * Lc;

    float C[2][4][4] = {};
    TN_MAINLOOP(Ah, Al, Bh, Bl);

    __syncthreads();
    float* Cst = (float*)smraw;  // 64 x 133
    {
        int wm = wid & 1, wn = wid >> 1;
        int lr = lane >> 2, lc = (lane & 3) * 2;
        #pragma unroll
        for (int mi = 0; mi < 2; ++mi)
            #pragma unroll
            for (int ni = 0; ni < 4; ++ni) {
                int rr = wm * 32 + mi * 16 + lr;
                int cc = wn * 32 + ni * 8 + lc;
                Cst[rr * 133 + cc] = C[mi][ni][0];
                Cst[rr * 133 + cc + 1] = C[mi][ni][1];
                Cst[(rr + 8) * 133 + cc] = C[mi][ni][2];
                Cst[(rr + 8) * 133 + cc + 1] = C[mi][ni][3];
            }
    }
    __syncthreads();
    #pragma unroll
    for (int rr = 0; rr < 16; ++rr) {
        int d = wid * 16 + rr;
        const float* cf = g_coefT + (size_t)(b * Dc + d) * Kc + k0;
        __nv_bfloat16* vh = d_VTh + (size_t)(b * Dc + d) * Kc + k0;
        __nv_bfloat16* vl = d_VTl + (size_t)(b * Dc + d) * Kc + k0;
        #pragma unroll
        for (int it = 0; it < 2; ++it) {
            int k = it * 32 + lane;
            float v = Cst[k * 133 + d] * cf[k];
            __nv_bfloat16 h, l;
            split2(v, h, l);
            vh[k] = h;
            vl[k] = l;
        }
    }
}

// GEMM2: D[l,d] = sum_k Eh[l][k]*VT[d][k]; silu*rnorm -> g_t
__global__ void __launch_bounds__(256, 1) gemm2_hmma() {
    extern __shared__ __align__(16) char smraw[];
    uint32_t sb = (uint32_t)__cvta_generic_to_shared(smraw);
    int tid = threadIdx.x, wid = tid >> 5, lane = tid & 31;
    int b = blockIdx.y, l0 = blockIdx.x * 64;

    const __nv_bfloat16* Ah = d_Eh + ((size_t)(b * Lc + l0)) * Kc;
    const __nv_bfloat16* Al = d_El + ((size_t)(b * Lc + l0)) * Kc;
    const __nv_bfloat16* Bh = d_VTh + (size_t)(b * Dc) * Kc;
    const __nv_bfloat16* Bl = d_VTl + (size_t)(b * Dc) * Kc;

    float C[2][4][4] = {};
    TN_MAINLOOP(Ah, Al, Bh, Bl);

    int wm = wid & 1, wn = wid >> 1;
    int lr = lane >> 2, lc = (lane & 3) * 2;
    #pragma unroll
    for (int mi = 0; mi < 2; ++mi) {
        int lg0 = l0 + wm * 32 + mi * 16 + lr;
        float rn0 = g_rnorm[b * Lc + lg0];
        float rn1 = g_rnorm[b * Lc + lg0 + 8];
        float* t0 = g_t + ((size_t)(b * Lc + lg0)) * Dc;
        float* t1 = t0 + 8 * Dc;
        #pragma unroll
        for (int ni = 0; ni < 4; ++ni) {
            int d = wn * 32 + ni * 8 + lc;
            float v0 = C[mi][ni][0] * rn0, v1 = C[mi][ni][1] * rn0;
            float v2 = C[mi][ni][2] * rn1, v3 = C[mi][ni][3] * rn1;
            *(float2*)(t0 + d) = make_float2(v0 * fsigmoid(v0), v1 * fsigmoid(v1));
            *(float2*)(t1 + d) = make_float2(v2 * fsigmoid(v2), v3 * fsigmoid(v3));
        }
    }
}

// ---------------- out_proj ----------------
__global__ void outproj_kernel(const float* __restrict__ Wout, const float* __restrict__ bout,
                               float* __restrict__ y) {
    int r0 = blockIdx.x * 64;
    __shared__ __align__(16) float As[16 * 68];
    __shared__ __align__(16) float Bs[16 * 128];
    int tid = threadIdx.x;
    int tx = tid & 15, ty = tid >> 4;
    float acc[4][8] = {};
    int am = tid >> 2, akq = tid & 3;
    int bd4 = tid & 31, bli = tid >> 5;

    for (int kt = 0; kt < Dc; kt += 16) {
        float4 av  = *(const float4*)(g_t + (size_t)(r0 + am) * Dc + kt + akq * 4);
        float4 bv0 = *(const float4*)(Wout + (kt + bli) * Dc + bd4 * 4);
        float4 bv1 = *(const float4*)(Wout + (kt + bli + 8) * Dc + bd4 * 4);
        __syncthreads();
        As[(akq * 4 + 0) * 68 + am] = av.x;
        As[(akq * 4 + 1) * 68 + am] = av.y;
        As[(akq * 4 + 2) * 68 + am] = av.z;
        As[(akq * 4 + 3) * 68 + am] = av.w;
        *(float4*)&Bs[bli * 128 + bd4 * 4] = bv0;
        *(float4*)&Bs[(bli + 8) * 128 + bd4 * 4] = bv1;
        __syncthreads();
        #pragma unroll
        for (int kk = 0; kk < 16; ++kk) {
            const float4 a = *(const float4*)&As[kk * 68 + ty * 4];
            const float4 p = *(const float4*)&Bs[kk * 128 + tx * 4];
            const float4 q = *(const float4*)&Bs[kk * 128 + tx * 4 + 64];
            float av4[4] = {a.x, a.y, a.z, a.w};
            float bv8[8] = {p.x, p.y, p.z, p.w, q.x, q.y, q.z, q.w};
            #pragma unroll
            for (int i = 0; i < 4; ++i)
                #pragma unroll
                for (int j = 0; j < 8; ++j)
                    acc[i][j] = fmaf(av4[i], bv8[j], acc[i][j]);
        }
    }
    #pragma unroll
    for (int i = 0; i < 4; ++i) {
        int row = r0 + ty * 4 + i;
        #pragma unroll
        for (int half = 0; half < 2; ++half) {
            float o[4];
            #pragma unroll
            for (int jj = 0; jj < 4; ++jj) {
                int n = tx * 4 + jj + half * 64;
                o[jj] = acc[i][half * 4 + jj] + bout[n];
            }
            *(float4*)(y + (size_t)row * Dc + tx * 4 + half * 64) =
                make_float4(o[0], o[1], o[2], o[3]);
        }
    }
}

extern "C" void kernel_launch(void* const* d_in, const int* in_sizes, int n_in,
                              void* d_out, int out_size) {
    const float* x       = (const float*)d_in[0];
    const float* E       = (const float*)d_in[2];
    const float* EigVals = (const float*)d_in[3];
    const float* bn_g    = (const float*)d_in[4];
    const float* bn_b    = (const float*)d_in[5];
    const float* bn_m    = (const float*)d_in[6];
    const float* bn_v    = (const float*)d_in[7];
    const float* W_in    = (const float*)d_in[8];
    const float* b_in    = (const float*)d_in[9];
    const float* logD    = (const float*)d_in[10];
    const float* Bp      = (const float*)d_in[11];
    const float* Cp      = (const float*)d_in[12];
    const float* logAr   = (const float*)d_in[13];
    const float* Aim     = (const float*)d_in[14];
    const float* Wout    = (const float*)d_in[15];
    const float* bout    = (const float*)d_in[16];
    float* y = (float*)d_out;

    cudaFuncSetAttribute(gemm1_hmma, cudaFuncAttributeMaxDynamicSharedMemorySize, SMEM_BYTES);
    cudaFuncSetAttribute(gemm2_hmma, cudaFuncAttributeMaxDynamicSharedMemorySize, SMEM_BYTES);

    front_kernel<<<7169, 256>>>(E, EigVals, bn_g, bn_b, bn_m, bn_v, W_in, b_in,
                                logD, Bp, Cp, logAr, Aim);
    uproj_kernel<<<ML / 64, 512>>>(x);
    gemm1_hmma<<<dim3(Kc / 64, Bc), 256, SMEM_BYTES>>>();
    gemm2_hmma<<<dim3(Lc / 64, Bc), 256, SMEM_BYTES>>>();
    outproj_kernel<<<ML / 64, 256>>>(Wout, bout, y);
}